// round 1
// baseline (speedup 1.0000x reference)
#include <cuda_runtime.h>
#include <cstdint>

// Problem constants (from reference): B=4, H=64, W=2650, C=64, N=680000
#define PB 4
#define PH 64
#define PW 2650
#define PC 64
#define PHW (PH * PW)          // 169600
#define PN 680000
#define THR 0.5f

// Scratch for BCHW -> BHWC transposed features. 4*169600*64 floats = ~174 MB.
// __device__ global array: the allowed way to get scratch (no cudaMalloc).
__device__ float g_featsT[(size_t)PB * PHW * PC];

// ---------------------------------------------------------------------------
// Kernel 1: transpose range_features [B, C, HW] -> [B, HW, C]
// Classic 32x32 smem tile, 32x8 threads, 4 rows/thread. Both global accesses
// fully coalesced. HW (169600) and C (64) are multiples of 32 -> no bounds.
// ---------------------------------------------------------------------------
__global__ void transpose_bchw_bhwc(const float* __restrict__ rf)
{
    __shared__ float tile[32][33];

    const int b      = blockIdx.z;
    const int cBase  = blockIdx.y * 32;
    const int hwBase = blockIdx.x * 32;

    const float* src = rf + (size_t)b * PC * PHW;
    float*       dst = g_featsT + (size_t)b * PHW * PC;

    const int tx = threadIdx.x;   // 0..31
    const int ty = threadIdx.y;   // 0..7

#pragma unroll
    for (int i = 0; i < 32; i += 8) {
        tile[ty + i][tx] = __ldg(&src[(size_t)(cBase + ty + i) * PHW + (hwBase + tx)]);
    }
    __syncthreads();
#pragma unroll
    for (int i = 0; i < 32; i += 8) {
        dst[(size_t)(hwBase + ty + i) * PC + (cBase + tx)] = tile[tx][ty + i];
    }
}

// ---------------------------------------------------------------------------
// Kernel 2: warp-per-point gather.
//   flat = b*HW + r*W + c
//   mask = seg[flat] >= THR
//   out[p, 0:5]  = points[p, :] * mask
//   out[p, 5:69] = featsT[flat, :] * mask    (contiguous 256B read)
//   mask_out[p]  = mask (as 1.0f / 0.0f)
// ---------------------------------------------------------------------------
__global__ void point_gather(const float* __restrict__ points,
                             const int*   __restrict__ ri,
                             const float* __restrict__ seg,
                             float* __restrict__ out,
                             float* __restrict__ mask_out)
{
    const int warp = (blockIdx.x * blockDim.x + threadIdx.x) >> 5;
    const int lane = threadIdx.x & 31;
    if (warp >= PN) return;

    const float* prow = points + (size_t)warp * 5;
    const int b = (int)__ldg(&prow[0]);
    const int r = __ldg(&ri[warp * 2 + 0]);
    const int c = __ldg(&ri[warp * 2 + 1]);
    const size_t flat = (size_t)b * PHW + (size_t)r * PW + (size_t)c;

    const float m = (__ldg(&seg[flat]) >= THR) ? 1.0f : 0.0f;

    const float* frow = g_featsT + flat * PC;
    float* orow = out + (size_t)warp * 69;

#pragma unroll
    for (int j = lane; j < 69; j += 32) {
        float v = (j < 5) ? __ldg(&prow[j]) : frow[j - 5];
        orow[j] = v * m;
    }
    if (lane == 0 && mask_out != nullptr) {
        mask_out[warp] = m;
    }
}

// ---------------------------------------------------------------------------
// Launch
// Inputs (metadata order): points [N,5] f32, ri_indices [N,2] i32,
//                          seg_pred [B,H,W] f32, range_features [B,C,H,W] f32
// Output: flattened (out [N,69], mask [N]) as float32.
// ---------------------------------------------------------------------------
extern "C" void kernel_launch(void* const* d_in, const int* in_sizes, int n_in,
                              void* d_out, int out_size)
{
    const float* points = (const float*)d_in[0];
    const int*   ri     = (const int*)  d_in[1];
    const float* seg    = (const float*)d_in[2];
    const float* rf     = (const float*)d_in[3];

    float* out = (float*)d_out;
    const int n = in_sizes[0] / 5;   // N = 680000

    // mask region follows the [N,69] block if the harness allotted space
    float* mask_out = nullptr;
    if ((long long)out_size >= (long long)n * 70)
        mask_out = out + (size_t)n * 69;

    // Kernel 1: transpose features into scratch
    {
        dim3 block(32, 8, 1);
        dim3 grid(PHW / 32, PC / 32, PB);   // (5300, 2, 4)
        transpose_bchw_bhwc<<<grid, block>>>(rf);
    }

    // Kernel 2: gather (warp per point)
    {
        const int threads = 256;                       // 8 warps per block
        const int warpsNeeded = n;
        const int blocks = (warpsNeeded + 7) / 8;      // 85000 blocks
        point_gather<<<blocks, threads>>>(points, ri, seg, out, mask_out);
    }
}

// round 2
// speedup vs baseline: 1.7492x; 1.7492x over previous
#include <cuda_runtime.h>
#include <cstdint>

// Problem constants (from reference): B=4, H=64, W=2650, C=64, N=680000
#define PB 4
#define PH 64
#define PW 2650
#define PC 64
#define PHW (PH * PW)          // 169600
#define THR 0.5f

// Scratch for BCHW -> BHWC transposed features (~174 MB).
__device__ float g_featsT[(size_t)PB * PHW * PC];

// ---------------------------------------------------------------------------
// Kernel 1: transpose range_features [B, C, HW] -> [B, HW, C]
// 32x32 smem tile, both sides coalesced. HW and C are multiples of 32.
// ---------------------------------------------------------------------------
__global__ void transpose_bchw_bhwc(const float* __restrict__ rf)
{
    __shared__ float tile[32][33];

    const int b      = blockIdx.z;
    const int cBase  = blockIdx.y * 32;
    const int hwBase = blockIdx.x * 32;

    const float* src = rf + (size_t)b * PC * PHW;
    float*       dst = g_featsT + (size_t)b * PHW * PC;

    const int tx = threadIdx.x;   // 0..31
    const int ty = threadIdx.y;   // 0..7

#pragma unroll
    for (int i = 0; i < 32; i += 8) {
        tile[ty + i][tx] = __ldg(&src[(size_t)(cBase + ty + i) * PHW + (hwBase + tx)]);
    }
    __syncthreads();
#pragma unroll
    for (int i = 0; i < 32; i += 8) {
        dst[(size_t)(hwBase + ty + i) * PC + (cBase + tx)] = tile[tx][ty + i];
    }
}

// ---------------------------------------------------------------------------
// Kernel 2: 4 points per warp, 32 points per 256-thread block.
//  - lanes 0..3 load the index chain (b, r, c, seg) for 4 points in parallel
//  - broadcast (flat, mask) via shfl; issue 4 independent 256B feature
//    gathers (float2 per lane) -> high MLP; skip the read when mask==0
//  - stage the 32x69 output tile in smem; write it back as 552 coalesced
//    float4 stores
// ---------------------------------------------------------------------------
__global__ __launch_bounds__(256) void point_gather(
    const float* __restrict__ points,
    const int*   __restrict__ ri,
    const float* __restrict__ seg,
    float*       __restrict__ out,
    float*       __restrict__ mask_out,
    int n)
{
    __shared__ float4 s4[552];                  // 32 * 69 floats = 2208 = 552 f4
    float* s = (float*)s4;

    const int tid   = threadIdx.x;
    const int warp  = tid >> 5;
    const int lane  = tid & 31;
    const int pBase = blockIdx.x * 32 + warp * 4;   // first point of this warp

    // --- index chain for 4 points on lanes 0..3 ---
    int   flat_i = 0;
    float m4     = 0.f;
    if (lane < 4) {
        const int p = pBase + lane;
        if (p < n) {
            const int b = (int)__ldg(&points[(size_t)p * 5]);
            const int r = __ldg(&ri[p * 2 + 0]);
            const int c = __ldg(&ri[p * 2 + 1]);
            flat_i = b * PHW + r * PW + c;
            m4 = (__ldg(&seg[flat_i]) >= THR) ? 1.0f : 0.0f;
        }
    }

    // --- 4 independent feature gathers (MLP=4 per lane) ---
    float2 v[4];
#pragma unroll
    for (int k = 0; k < 4; k++) {
        const int   fl = __shfl_sync(0xffffffffu, flat_i, k);
        const float m  = __shfl_sync(0xffffffffu, m4,     k);
        v[k] = make_float2(0.f, 0.f);
        if (m != 0.f)
            v[k] = __ldg((const float2*)(g_featsT + (size_t)fl * PC) + lane);
    }

    // --- stage features into smem ---
#pragma unroll
    for (int k = 0; k < 4; k++) {
        float* row = s + (warp * 4 + k) * 69 + 5;
        row[2 * lane + 0] = v[k].x;
        row[2 * lane + 1] = v[k].y;
    }

    // --- stage the 5 point columns (masked) ---
    const float m_pt = __shfl_sync(0xffffffffu, m4, (lane < 20) ? (lane / 5) : 0);
    if (lane < 20) {
        const int k = lane / 5;
        const int j = lane - k * 5;
        const int p = pBase + k;
        const float val = (p < n) ? __ldg(&points[(size_t)p * 5 + j]) : 0.f;
        s[(warp * 4 + k) * 69 + j] = val * m_pt;
    }

    // --- mask output ---
    if (lane < 4 && mask_out != nullptr && (pBase + lane) < n)
        mask_out[pBase + lane] = m4;

    __syncthreads();

    // --- coalesced float4 writeback of the whole 32x69 tile ---
    const size_t outF4 = ((size_t)n * 69) >> 2;          // total float4s in out
    float4* dst = (float4*)out + (size_t)blockIdx.x * 552;
#pragma unroll 3
    for (int i = tid; i < 552; i += 256) {
        const size_t g = (size_t)blockIdx.x * 552 + i;
        if (g < outF4) dst[i] = s4[i];
    }
}

// ---------------------------------------------------------------------------
// Launch
// Inputs (metadata order): points [N,5] f32, ri_indices [N,2] i32,
//                          seg_pred [B,H,W] f32, range_features [B,C,H,W] f32
// Output: flattened (out [N,69], mask [N]) as float32.
// ---------------------------------------------------------------------------
extern "C" void kernel_launch(void* const* d_in, const int* in_sizes, int n_in,
                              void* d_out, int out_size)
{
    const float* points = (const float*)d_in[0];
    const int*   ri     = (const int*)  d_in[1];
    const float* seg    = (const float*)d_in[2];
    const float* rf     = (const float*)d_in[3];

    float* out = (float*)d_out;
    const int n = in_sizes[0] / 5;   // N = 680000

    float* mask_out = nullptr;
    if ((long long)out_size >= (long long)n * 70)
        mask_out = out + (size_t)n * 69;

    // Kernel 1: transpose features into scratch
    {
        dim3 block(32, 8, 1);
        dim3 grid(PHW / 32, PC / 32, PB);   // (5300, 2, 4)
        transpose_bchw_bhwc<<<grid, block>>>(rf);
    }

    // Kernel 2: gather (4 points per warp, smem-staged coalesced output)
    {
        const int blocks = (n + 31) / 32;   // 21250 for N=680000
        point_gather<<<blocks, 256>>>(points, ri, seg, out, mask_out, n);
    }
}

// round 3
// speedup vs baseline: 2.2247x; 1.2719x over previous
#include <cuda_runtime.h>
#include <cstdint>

// Problem constants: B=4, H=64, W=2650, C=64, N=680000
#define PB 4
#define PH 64
#define PW 2650
#define PC 64
#define PHW (PH * PW)          // 169600
#define THR 0.5f

// Scratch for BCHW -> BHWC transposed features (~174 MB).
__device__ float g_featsT[(size_t)PB * PHW * PC];

// ---------------------------------------------------------------------------
// Kernel 1: mask-aware vectorized transpose [B, C, HW] -> [B, HW, C]
// Tile: 32 hw x 64 C, 256 threads. float4 on both sides.
// Rows whose seg < THR are never read by the gather -> skip their writes.
// ---------------------------------------------------------------------------
__global__ __launch_bounds__(256) void transpose_bchw_bhwc(
    const float* __restrict__ rf,
    const float* __restrict__ seg)
{
    __shared__ float s[32 * 65];          // [hw][c] padded: bank-conflict free

    const int b      = blockIdx.y;
    const int hwBase = blockIdx.x * 32;

    const int t   = threadIdx.x;
    const int cR  = t >> 3;               // 0..31  (c row for load)
    const int f4  = t & 7;                // 0..7   (float4 index within 32 floats)

    const float* src = rf + (size_t)b * PC * PHW + hwBase;

    // --- load: 64 c-rows x 32 hw floats, float4, fully coalesced ---
#pragma unroll
    for (int half = 0; half < 2; half++) {
        const int c = cR + half * 32;
        const float4 v = __ldg((const float4*)(src + (size_t)c * PHW) + f4);
        // transposed smem store: s[hw][c], conflict-free (stride 65)
        s[(f4 * 4 + 0) * 65 + c] = v.x;
        s[(f4 * 4 + 1) * 65 + c] = v.y;
        s[(f4 * 4 + 2) * 65 + c] = v.z;
        s[(f4 * 4 + 3) * 65 + c] = v.w;
    }
    __syncthreads();

    // --- write: 32 hw-rows x 64 c floats, float4, skip bg rows ---
    const int rowA = t >> 3;              // 0..31 hw row
    const bool fg = __ldg(&seg[(size_t)b * PHW + hwBase + rowA]) >= THR;
    if (fg) {
        float4* dst = (float4*)(g_featsT + ((size_t)b * PHW + hwBase + rowA) * PC);
#pragma unroll
        for (int half = 0; half < 2; half++) {
            const int f = f4 + half * 8;  // 0..15 float4 within 64-float row
            float4 v;
            v.x = s[rowA * 65 + f * 4 + 0];
            v.y = s[rowA * 65 + f * 4 + 1];
            v.z = s[rowA * 65 + f * 4 + 2];
            v.w = s[rowA * 65 + f * 4 + 3];
            dst[f] = v;
        }
    }
}

// ---------------------------------------------------------------------------
// Kernel 2: 8 points per warp, direct register->gmem writes (no smem).
//  - lanes 0..7 run the index chain for 8 points in parallel
//  - 8 independent 256B feature gathers per warp (float2/lane), skipped for
//    bg points (value 0)
//  - features written as per-point contiguous ~264B warp stores
// ---------------------------------------------------------------------------
__global__ __launch_bounds__(256) void point_gather(
    const float* __restrict__ points,
    const int*   __restrict__ ri,
    const float* __restrict__ seg,
    float*       __restrict__ out,
    float*       __restrict__ mask_out,
    int n)
{
    const int tid   = threadIdx.x;
    const int warp  = tid >> 5;
    const int lane  = tid & 31;
    const int pBase = blockIdx.x * 64 + warp * 8;   // first point of this warp

    // --- index chain for 8 points on lanes 0..7 ---
    int   flat_i = 0;
    float m8     = 0.f;
    if (lane < 8) {
        const int p = pBase + lane;
        if (p < n) {
            const int b = (int)__ldg(&points[(size_t)p * 5]);
            const int r = __ldg(&ri[p * 2 + 0]);
            const int c = __ldg(&ri[p * 2 + 1]);
            flat_i = b * PHW + r * PW + c;
            m8 = (__ldg(&seg[flat_i]) >= THR) ? 1.0f : 0.0f;
        }
    }

    // --- 8 independent feature gathers (MLP=8 per lane) ---
    float2 v[8];
    int   fls[8];
    float ms[8];
#pragma unroll
    for (int k = 0; k < 8; k++) {
        fls[k] = __shfl_sync(0xffffffffu, flat_i, k);
        ms[k]  = __shfl_sync(0xffffffffu, m8,     k);
        v[k] = make_float2(0.f, 0.f);
        if (ms[k] != 0.f)
            v[k] = __ldg((const float2*)(g_featsT + (size_t)fls[k] * PC) + lane);
    }

    // --- feature writeback: per-point contiguous 256B warp store ---
#pragma unroll
    for (int k = 0; k < 8; k++) {
        const int p = pBase + k;
        if (p < n) {
            float* row = out + (size_t)p * 69 + 5;
            row[2 * lane + 0] = v[k].x;
            row[2 * lane + 1] = v[k].y;
        }
    }

    // --- point columns 0..4 (masked): 8 points x 5 cols = 40 values ---
#pragma unroll
    for (int half = 0; half < 2; half++) {
        const int idx = half * 32 + lane;       // 0..63, use 0..39
        if (idx < 40) {
            const int k = idx / 5;
            const int j = idx - k * 5;
            const int p = pBase + k;
            if (p < n)
                out[(size_t)p * 69 + j] = __ldg(&points[(size_t)p * 5 + j]) * ms[k];
        }
    }

    // --- mask output: lanes 0..7, 32B-aligned sector ---
    if (lane < 8 && mask_out != nullptr && (pBase + lane) < n)
        mask_out[pBase + lane] = m8;
}

// ---------------------------------------------------------------------------
// Launch
// Inputs: points [N,5] f32, ri_indices [N,2] i32,
//         seg_pred [B,H,W] f32, range_features [B,C,H,W] f32
// Output: flattened (out [N,69], mask [N]) as float32.
// ---------------------------------------------------------------------------
extern "C" void kernel_launch(void* const* d_in, const int* in_sizes, int n_in,
                              void* d_out, int out_size)
{
    const float* points = (const float*)d_in[0];
    const int*   ri     = (const int*)  d_in[1];
    const float* seg    = (const float*)d_in[2];
    const float* rf     = (const float*)d_in[3];

    float* out = (float*)d_out;
    const int n = in_sizes[0] / 5;   // N = 680000

    float* mask_out = nullptr;
    if ((long long)out_size >= (long long)n * 70)
        mask_out = out + (size_t)n * 69;

    // Kernel 1: mask-aware vectorized transpose
    {
        dim3 grid(PHW / 32, PB, 1);   // (5300, 4)
        transpose_bchw_bhwc<<<grid, 256>>>(rf, seg);
    }

    // Kernel 2: gather (8 points per warp, direct writes)
    {
        const int blocks = (n + 63) / 64;   // 10625
        point_gather<<<blocks, 256>>>(points, ri, seg, out, mask_out, n);
    }
}

// round 4
// speedup vs baseline: 2.4413x; 1.0974x over previous
#include <cuda_runtime.h>
#include <cuda_fp16.h>
#include <cstdint>

// Problem constants: B=4, H=64, W=2650, C=64, N=680000
#define PB 4
#define PH 64
#define PW 2650
#define PC 64
#define PHW (PH * PW)          // 169600
#define THR 0.5f

// Scratch for BCHW -> BHWC transposed features, fp16 (~87 MB).
__device__ __half g_featsT[(size_t)PB * PHW * PC];

// ---------------------------------------------------------------------------
// Kernel 1: mask-aware transpose [B, C, HW] f32 -> [B, HW, C] f16
// Tile: 32 hw x 64 C, 256 threads. float4 loads, 16B packed-half stores.
// Rows whose seg < THR are never read by the gather -> skip their writes.
// ---------------------------------------------------------------------------
__global__ __launch_bounds__(256) void transpose_bchw_bhwc(
    const float* __restrict__ rf,
    const float* __restrict__ seg)
{
    __shared__ float s[32 * 65];          // [hw][c] padded

    const int b      = blockIdx.y;
    const int hwBase = blockIdx.x * 32;

    const int t  = threadIdx.x;
    const int cR = t >> 3;                // 0..31
    const int f4 = t & 7;                 // 0..7

    const float* src = rf + (size_t)b * PC * PHW + hwBase;

    // --- load: 64 c-rows x 32 hw floats, float4, fully coalesced ---
#pragma unroll
    for (int half_ = 0; half_ < 2; half_++) {
        const int c = cR + half_ * 32;
        const float4 v = __ldg((const float4*)(src + (size_t)c * PHW) + f4);
        s[(f4 * 4 + 0) * 65 + c] = v.x;
        s[(f4 * 4 + 1) * 65 + c] = v.y;
        s[(f4 * 4 + 2) * 65 + c] = v.z;
        s[(f4 * 4 + 3) * 65 + c] = v.w;
    }
    __syncthreads();

    // --- write: 32 hw-rows x 64 halves, 8 halves (16B) per thread ---
    const int row = t >> 3;               // 0..31
    const int q   = t & 7;                // 0..7 : 16B chunk within row
    const bool fg = __ldg(&seg[(size_t)b * PHW + hwBase + row]) >= THR;
    if (fg) {
        const float* sr = s + row * 65 + q * 8;
        half2 h0 = __floats2half2_rn(sr[0], sr[1]);
        half2 h1 = __floats2half2_rn(sr[2], sr[3]);
        half2 h2 = __floats2half2_rn(sr[4], sr[5]);
        half2 h3 = __floats2half2_rn(sr[6], sr[7]);
        uint4 pack;
        pack.x = *(const unsigned*)&h0;
        pack.y = *(const unsigned*)&h1;
        pack.z = *(const unsigned*)&h2;
        pack.w = *(const unsigned*)&h3;
        uint4* dst = (uint4*)(g_featsT + ((size_t)b * PHW + hwBase + row) * PC);
        dst[q] = pack;
    }
}

// ---------------------------------------------------------------------------
// Kernel 2: 8 points per warp, fp16 feature reads, direct writes.
//  - lanes 0..7 run the index chain for 8 points in parallel
//  - 8 independent 128B half2 gathers per warp (4B/lane), skipped for bg
//  - features converted to f32 and written as per-point contiguous stores
// ---------------------------------------------------------------------------
__global__ __launch_bounds__(256) void point_gather(
    const float* __restrict__ points,
    const int*   __restrict__ ri,
    const float* __restrict__ seg,
    float*       __restrict__ out,
    float*       __restrict__ mask_out,
    int n)
{
    const int tid   = threadIdx.x;
    const int warp  = tid >> 5;
    const int lane  = tid & 31;
    const int pBase = blockIdx.x * 64 + warp * 8;

    // --- index chain for 8 points on lanes 0..7 ---
    int   flat_i = 0;
    float m8     = 0.f;
    if (lane < 8) {
        const int p = pBase + lane;
        if (p < n) {
            const int b = (int)__ldg(&points[(size_t)p * 5]);
            const int r = __ldg(&ri[p * 2 + 0]);
            const int c = __ldg(&ri[p * 2 + 1]);
            flat_i = b * PHW + r * PW + c;
            m8 = (__ldg(&seg[flat_i]) >= THR) ? 1.0f : 0.0f;
        }
    }

    // --- 8 independent half2 feature gathers (MLP=8 per lane) ---
    half2 v[8];
    int   fls[8];
    float ms[8];
#pragma unroll
    for (int k = 0; k < 8; k++) {
        fls[k] = __shfl_sync(0xffffffffu, flat_i, k);
        ms[k]  = __shfl_sync(0xffffffffu, m8,     k);
        v[k] = __floats2half2_rn(0.f, 0.f);
        if (ms[k] != 0.f)
            v[k] = __ldg((const half2*)(g_featsT + (size_t)fls[k] * PC) + lane);
    }

    // --- feature writeback: per-point contiguous ~256B warp store ---
#pragma unroll
    for (int k = 0; k < 8; k++) {
        const int p = pBase + k;
        if (p < n) {
            const float2 f = __half22float2(v[k]);
            float* row = out + (size_t)p * 69 + 5;
            row[2 * lane + 0] = f.x;
            row[2 * lane + 1] = f.y;
        }
    }

    // --- point columns 0..4 (masked): 8 points x 5 cols = 40 values ---
#pragma unroll
    for (int half_ = 0; half_ < 2; half_++) {
        const int idx = half_ * 32 + lane;
        if (idx < 40) {
            const int k = idx / 5;
            const int j = idx - k * 5;
            const int p = pBase + k;
            if (p < n)
                out[(size_t)p * 69 + j] = __ldg(&points[(size_t)p * 5 + j]) * ms[k];
        }
    }

    // --- mask output ---
    if (lane < 8 && mask_out != nullptr && (pBase + lane) < n)
        mask_out[pBase + lane] = m8;
}

// ---------------------------------------------------------------------------
// Launch
// ---------------------------------------------------------------------------
extern "C" void kernel_launch(void* const* d_in, const int* in_sizes, int n_in,
                              void* d_out, int out_size)
{
    const float* points = (const float*)d_in[0];
    const int*   ri     = (const int*)  d_in[1];
    const float* seg    = (const float*)d_in[2];
    const float* rf     = (const float*)d_in[3];

    float* out = (float*)d_out;
    const int n = in_sizes[0] / 5;   // N = 680000

    float* mask_out = nullptr;
    if ((long long)out_size >= (long long)n * 70)
        mask_out = out + (size_t)n * 69;

    // Kernel 1: mask-aware transpose (f32 -> f16 scratch)
    {
        dim3 grid(PHW / 32, PB, 1);   // (5300, 4)
        transpose_bchw_bhwc<<<grid, 256>>>(rf, seg);
    }

    // Kernel 2: gather (8 points per warp, half2 reads, direct writes)
    {
        const int blocks = (n + 63) / 64;   // 10625
        point_gather<<<blocks, 256>>>(points, ri, seg, out, mask_out, n);
    }
}